// round 1
// baseline (speedup 1.0000x reference)
#include <cuda_runtime.h>
#include <cuda_bf16.h>
#include <math.h>

// ---------------------------------------------------------------------------
// Problem constants
// ---------------------------------------------------------------------------
#define BATCH   8
#define SEQ     1024
#define ROWS    (BATCH * SEQ)        // 8192
#define EMBED   768
#define HEADS   12
#define HDIM    64
#define QKDIM   (2 * EMBED)          // 1536
#define MLPDIM  3072
#define BH      (BATCH * HEADS)      // 96

// ---------------------------------------------------------------------------
// Device scratch (static globals — allocation-free)
// ---------------------------------------------------------------------------
__device__ float g_h1[(size_t)ROWS * EMBED];           // LN1 output
__device__ float g_qk[(size_t)ROWS * QKDIM];           // QK projection
__device__ float g_v [(size_t)ROWS * EMBED];           // V projection
__device__ float g_sc[(size_t)BH * SEQ * SEQ];         // attention scores (402 MB)
__device__ float g_att[(size_t)ROWS * EMBED];          // attention output (merged heads)
__device__ float g_x2[(size_t)ROWS * EMBED];           // x + proj
__device__ float g_h2[(size_t)ROWS * EMBED];           // LN2 output
__device__ float g_m1[(size_t)ROWS * MLPDIM];          // GELU(fc1)

// ---------------------------------------------------------------------------
// LayerNorm: one block per row (768 elems, 256 threads x 3)
// ---------------------------------------------------------------------------
__global__ __launch_bounds__(256)
void ln_kernel(const float* __restrict__ x, const float* __restrict__ g,
               const float* __restrict__ b, float* __restrict__ out)
{
    __shared__ float s1[8], s2[8];
    const long row = blockIdx.x;
    const float* p = x + row * EMBED;
    const int tid = threadIdx.x;

    float v0 = p[tid], v1 = p[tid + 256], v2 = p[tid + 512];
    float s = v0 + v1 + v2;
    float q = v0 * v0 + v1 * v1 + v2 * v2;
    #pragma unroll
    for (int o = 16; o; o >>= 1) {
        s += __shfl_xor_sync(0xFFFFFFFFu, s, o);
        q += __shfl_xor_sync(0xFFFFFFFFu, q, o);
    }
    if ((tid & 31) == 0) { s1[tid >> 5] = s; s2[tid >> 5] = q; }
    __syncthreads();
    if (tid < 32) {
        s = (tid < 8) ? s1[tid] : 0.0f;
        q = (tid < 8) ? s2[tid] : 0.0f;
        #pragma unroll
        for (int o = 4; o; o >>= 1) {
            s += __shfl_xor_sync(0xFFFFFFFFu, s, o);
            q += __shfl_xor_sync(0xFFFFFFFFu, q, o);
        }
        if (tid == 0) { s1[0] = s; s2[0] = q; }
    }
    __syncthreads();
    const float inv = 1.0f / (float)EMBED;
    const float mu  = s1[0] * inv;
    const float var = s2[0] * inv - mu * mu;
    const float rstd = rsqrtf(var + 1e-5f);
    float* po = out + row * EMBED;
    po[tid      ] = (v0 - mu) * rstd * g[tid      ] + b[tid      ];
    po[tid + 256] = (v1 - mu) * rstd * g[tid + 256] + b[tid + 256];
    po[tid + 512] = (v2 - mu) * rstd * g[tid + 512] + b[tid + 512];
}

// ---------------------------------------------------------------------------
// Tiled fp32 GEMM: C[M,N] = A[M,K] @ B[K,N]  (+ epilogue)
// 128x128 block tile, K-tile 8, 256 threads, 8x8 micro-tile.
// EPI: 0 = none, 1 = bias, 2 = bias + exact GELU, 3 = bias + residual add
// ---------------------------------------------------------------------------
#define EPI_NONE     0
#define EPI_BIAS     1
#define EPI_GELU     2
#define EPI_BIASRES  3

template<int EPI>
__global__ __launch_bounds__(256)
void gemm_f32(const float* __restrict__ A, const float* __restrict__ B,
              const float* __restrict__ bias, const float* __restrict__ res,
              float* __restrict__ C, int M, int N, int K)
{
    __shared__ float As[8][128];
    __shared__ float Bs[8][128];

    const int tid = threadIdx.x;
    const int bm = blockIdx.y * 128;
    const int bn = blockIdx.x * 128;
    const int tx = tid & 15;
    const int ty = tid >> 4;

    // A loader: thread -> (row, quad)
    const int ar = tid >> 1;
    const int aq = (tid & 1) * 4;
    // B loader: thread -> (krow, col4)
    const int br = tid >> 5;
    const int bc = (tid & 31) * 4;

    float acc[8][8];
    #pragma unroll
    for (int i = 0; i < 8; i++)
        #pragma unroll
        for (int j = 0; j < 8; j++) acc[i][j] = 0.0f;

    for (int k0 = 0; k0 < K; k0 += 8) {
        float4 av = *(const float4*)(A + (long)(bm + ar) * K + k0 + aq);
        As[aq + 0][ar] = av.x;
        As[aq + 1][ar] = av.y;
        As[aq + 2][ar] = av.z;
        As[aq + 3][ar] = av.w;
        *(float4*)&Bs[br][bc] = *(const float4*)(B + (long)(k0 + br) * N + bn + bc);
        __syncthreads();

        #pragma unroll
        for (int kk = 0; kk < 8; kk++) {
            float a[8], bb[8];
            *(float4*)&a[0]  = *(const float4*)&As[kk][ty * 8];
            *(float4*)&a[4]  = *(const float4*)&As[kk][ty * 8 + 4];
            *(float4*)&bb[0] = *(const float4*)&Bs[kk][tx * 8];
            *(float4*)&bb[4] = *(const float4*)&Bs[kk][tx * 8 + 4];
            #pragma unroll
            for (int i = 0; i < 8; i++)
                #pragma unroll
                for (int j = 0; j < 8; j++)
                    acc[i][j] = fmaf(a[i], bb[j], acc[i][j]);
        }
        __syncthreads();
    }

    // epilogue
    float bv[8];
    if (EPI != EPI_NONE) {
        #pragma unroll
        for (int j = 0; j < 8; j++) bv[j] = bias[bn + tx * 8 + j];
    }
    #pragma unroll
    for (int i = 0; i < 8; i++) {
        const long base = (long)(bm + ty * 8 + i) * N + bn + tx * 8;
        float out[8];
        #pragma unroll
        for (int j = 0; j < 8; j++) {
            float c = acc[i][j];
            if (EPI != EPI_NONE) c += bv[j];
            if (EPI == EPI_GELU) c = 0.5f * c * (1.0f + erff(c * 0.70710678118654752f));
            if (EPI == EPI_BIASRES) c += res[base + j];
            out[j] = c;
        }
        *(float4*)(C + base)     = *(float4*)&out[0];
        *(float4*)(C + base + 4) = *(float4*)&out[4];
    }
}

// ---------------------------------------------------------------------------
// Attention scores: S[bh, n, m] = (Q[bh,n,:] . K[bh,m,:]) / 8
// Q, K live inside g_qk: row (b*SEQ+n), q cols h*64.., k cols 768+h*64..
// Block computes 64x64 tile. grid = (16, 16, 96), 256 threads.
// ---------------------------------------------------------------------------
__global__ __launch_bounds__(256)
void attn_scores(const float* __restrict__ qk, float* __restrict__ sc)
{
    const int bh = blockIdx.z;
    const int b = bh / HEADS, h = bh % HEADS;
    const float* Qb = qk + (long)b * SEQ * QKDIM + h * HDIM;
    const float* Kb = Qb + EMBED;
    const int n0 = blockIdx.y * 64;
    const int m0 = blockIdx.x * 64;
    const int tid = threadIdx.x;

    __shared__ float Qs[64][65];
    __shared__ float Ks[64][65];

    #pragma unroll
    for (int i = 0; i < 4; i++) {
        int idx = tid + i * 256;
        int r = idx >> 4;
        int c = (idx & 15) * 4;
        float4 qv = *(const float4*)(Qb + (long)(n0 + r) * QKDIM + c);
        Qs[r][c] = qv.x; Qs[r][c+1] = qv.y; Qs[r][c+2] = qv.z; Qs[r][c+3] = qv.w;
        float4 kv = *(const float4*)(Kb + (long)(m0 + r) * QKDIM + c);
        Ks[r][c] = kv.x; Ks[r][c+1] = kv.y; Ks[r][c+2] = kv.z; Ks[r][c+3] = kv.w;
    }
    __syncthreads();

    const int tx = tid & 15, ty = tid >> 4;
    float acc[4][4];
    #pragma unroll
    for (int i = 0; i < 4; i++)
        #pragma unroll
        for (int j = 0; j < 4; j++) acc[i][j] = 0.0f;

    #pragma unroll 8
    for (int d = 0; d < HDIM; d++) {
        float a[4], bb[4];
        #pragma unroll
        for (int i = 0; i < 4; i++) a[i]  = Qs[ty * 4 + i][d];
        #pragma unroll
        for (int j = 0; j < 4; j++) bb[j] = Ks[tx * 4 + j][d];
        #pragma unroll
        for (int i = 0; i < 4; i++)
            #pragma unroll
            for (int j = 0; j < 4; j++)
                acc[i][j] = fmaf(a[i], bb[j], acc[i][j]);
    }

    #pragma unroll
    for (int i = 0; i < 4; i++) {
        float out[4];
        #pragma unroll
        for (int j = 0; j < 4; j++) out[j] = acc[i][j] * 0.125f;
        long base = ((long)bh * SEQ + n0 + ty * 4 + i) * SEQ + m0 + tx * 4;
        *(float4*)(sc + base) = *(float4*)&out[0];
    }
}

// ---------------------------------------------------------------------------
// Row softmax over 1024 elements. One block per row, 256 threads x 4.
// ---------------------------------------------------------------------------
__global__ __launch_bounds__(256)
void softmax_rows(float* __restrict__ sc)
{
    __shared__ float sh[8];
    __shared__ float bcast;
    const long row = blockIdx.x;
    float* p = sc + row * SEQ;
    const int tid = threadIdx.x;

    float4 v = *(float4*)(p + tid * 4);
    float m = fmaxf(fmaxf(v.x, v.y), fmaxf(v.z, v.w));
    #pragma unroll
    for (int o = 16; o; o >>= 1) m = fmaxf(m, __shfl_xor_sync(0xFFFFFFFFu, m, o));
    if ((tid & 31) == 0) sh[tid >> 5] = m;
    __syncthreads();
    if (tid < 32) {
        m = (tid < 8) ? sh[tid] : -INFINITY;
        #pragma unroll
        for (int o = 4; o; o >>= 1) m = fmaxf(m, __shfl_xor_sync(0xFFFFFFFFu, m, o));
        if (tid == 0) bcast = m;
    }
    __syncthreads();
    m = bcast;

    v.x = __expf(v.x - m); v.y = __expf(v.y - m);
    v.z = __expf(v.z - m); v.w = __expf(v.w - m);
    float s = v.x + v.y + v.z + v.w;
    #pragma unroll
    for (int o = 16; o; o >>= 1) s += __shfl_xor_sync(0xFFFFFFFFu, s, o);
    __syncthreads();
    if ((tid & 31) == 0) sh[tid >> 5] = s;
    __syncthreads();
    if (tid < 32) {
        s = (tid < 8) ? sh[tid] : 0.0f;
        #pragma unroll
        for (int o = 4; o; o >>= 1) s += __shfl_xor_sync(0xFFFFFFFFu, s, o);
        if (tid == 0) bcast = s;
    }
    __syncthreads();
    const float inv = 1.0f / bcast;
    v.x *= inv; v.y *= inv; v.z *= inv; v.w *= inv;
    *(float4*)(p + tid * 4) = v;
}

// ---------------------------------------------------------------------------
// O = softmax(S) @ V, written directly in head-merged [ROWS, EMBED] layout.
// Block: 64 query rows x full head dim (64). grid = (16, 96), 256 threads.
// ---------------------------------------------------------------------------
__global__ __launch_bounds__(256)
void attn_av(const float* __restrict__ sc, const float* __restrict__ v,
             float* __restrict__ out)
{
    const int bh = blockIdx.y;
    const int b = bh / HEADS, h = bh % HEADS;
    const int n0 = blockIdx.x * 64;
    const float* S  = sc + (long)bh * SEQ * SEQ;
    const float* Vb = v + (long)b * SEQ * EMBED + h * HDIM;
    const int tid = threadIdx.x;
    const int tx = tid & 15, ty = tid >> 4;

    __shared__ float Ss[64][65];
    __shared__ float Vs[64][65];

    float acc[4][4];
    #pragma unroll
    for (int i = 0; i < 4; i++)
        #pragma unroll
        for (int j = 0; j < 4; j++) acc[i][j] = 0.0f;

    for (int m0 = 0; m0 < SEQ; m0 += 64) {
        #pragma unroll
        for (int i = 0; i < 4; i++) {
            int idx = tid + i * 256;
            int r = idx >> 4;
            int c = (idx & 15) * 4;
            float4 sv = *(const float4*)(S + (long)(n0 + r) * SEQ + m0 + c);
            Ss[r][c] = sv.x; Ss[r][c+1] = sv.y; Ss[r][c+2] = sv.z; Ss[r][c+3] = sv.w;
            float4 vv = *(const float4*)(Vb + (long)(m0 + r) * EMBED + c);
            Vs[r][c] = vv.x; Vs[r][c+1] = vv.y; Vs[r][c+2] = vv.z; Vs[r][c+3] = vv.w;
        }
        __syncthreads();

        #pragma unroll 8
        for (int kk = 0; kk < 64; kk++) {
            float a[4], bb[4];
            #pragma unroll
            for (int i = 0; i < 4; i++) a[i]  = Ss[ty * 4 + i][kk];
            #pragma unroll
            for (int j = 0; j < 4; j++) bb[j] = Vs[kk][tx * 4 + j];
            #pragma unroll
            for (int i = 0; i < 4; i++)
                #pragma unroll
                for (int j = 0; j < 4; j++)
                    acc[i][j] = fmaf(a[i], bb[j], acc[i][j]);
        }
        __syncthreads();
    }

    #pragma unroll
    for (int i = 0; i < 4; i++) {
        long base = (long)(b * SEQ + n0 + ty * 4 + i) * EMBED + h * HDIM + tx * 4;
        *(float4*)(out + base) = *(float4*)&acc[i][0];
    }
}

// ---------------------------------------------------------------------------
// Launch
// ---------------------------------------------------------------------------
extern "C" void kernel_launch(void* const* d_in, const int* in_sizes, int n_in,
                              void* d_out, int out_size)
{
    const float* x      = (const float*)d_in[0];
    const float* ln1_g  = (const float*)d_in[1];
    const float* ln1_b  = (const float*)d_in[2];
    const float* qk_w   = (const float*)d_in[3];
    const float* v_w    = (const float*)d_in[4];
    const float* proj_w = (const float*)d_in[5];
    const float* proj_b = (const float*)d_in[6];
    const float* ln2_g  = (const float*)d_in[7];
    const float* ln2_b  = (const float*)d_in[8];
    const float* fc1_w  = (const float*)d_in[9];
    const float* fc1_b  = (const float*)d_in[10];
    const float* fc2_w  = (const float*)d_in[11];
    const float* fc2_b  = (const float*)d_in[12];
    float* out = (float*)d_out;

    float *h1, *qkb, *vb, *sc, *att, *x2, *h2, *m1;
    cudaGetSymbolAddress((void**)&h1,  g_h1);
    cudaGetSymbolAddress((void**)&qkb, g_qk);
    cudaGetSymbolAddress((void**)&vb,  g_v);
    cudaGetSymbolAddress((void**)&sc,  g_sc);
    cudaGetSymbolAddress((void**)&att, g_att);
    cudaGetSymbolAddress((void**)&x2,  g_x2);
    cudaGetSymbolAddress((void**)&h2,  g_h2);
    cudaGetSymbolAddress((void**)&m1,  g_m1);

    // --- attention branch ---
    ln_kernel<<<ROWS, 256>>>(x, ln1_g, ln1_b, h1);

    gemm_f32<EPI_NONE><<<dim3(QKDIM / 128, ROWS / 128), 256>>>(
        h1, qk_w, nullptr, nullptr, qkb, ROWS, QKDIM, EMBED);
    gemm_f32<EPI_NONE><<<dim3(EMBED / 128, ROWS / 128), 256>>>(
        h1, v_w, nullptr, nullptr, vb, ROWS, EMBED, EMBED);

    attn_scores<<<dim3(SEQ / 64, SEQ / 64, BH), 256>>>(qkb, sc);
    softmax_rows<<<(long)BH * SEQ, 256>>>(sc);
    attn_av<<<dim3(SEQ / 64, BH), 256>>>(sc, vb, att);

    gemm_f32<EPI_BIASRES><<<dim3(EMBED / 128, ROWS / 128), 256>>>(
        att, proj_w, proj_b, x, x2, ROWS, EMBED, EMBED);

    // --- MLP branch ---
    ln_kernel<<<ROWS, 256>>>(x2, ln2_g, ln2_b, h2);

    gemm_f32<EPI_GELU><<<dim3(MLPDIM / 128, ROWS / 128), 256>>>(
        h2, fc1_w, fc1_b, nullptr, m1, ROWS, MLPDIM, EMBED);

    gemm_f32<EPI_BIASRES><<<dim3(EMBED / 128, ROWS / 128), 256>>>(
        m1, fc2_w, fc2_b, x2, out, ROWS, EMBED, MLPDIM);
}

// round 2
// speedup vs baseline: 2.0277x; 2.0277x over previous
#include <cuda_runtime.h>
#include <cuda_bf16.h>
#include <math.h>
#include <stdint.h>

// ---------------------------------------------------------------------------
// Problem constants
// ---------------------------------------------------------------------------
#define BATCH   8
#define SEQ     1024
#define ROWS    (BATCH * SEQ)        // 8192
#define EMBED   768
#define HEADS   12
#define HDIM    64
#define QKDIM   (2 * EMBED)          // 1536
#define MLPDIM  3072
#define BH      (BATCH * HEADS)      // 96

// ---------------------------------------------------------------------------
// Device scratch (static globals — allocation-free)
// ---------------------------------------------------------------------------
__device__ float g_h1[(size_t)ROWS * EMBED];
__device__ float g_qk[(size_t)ROWS * QKDIM];
__device__ float g_v [(size_t)ROWS * EMBED];
__device__ float g_sc[(size_t)BH * SEQ * SEQ];
__device__ float g_att[(size_t)ROWS * EMBED];
__device__ float g_x2[(size_t)ROWS * EMBED];
__device__ float g_h2[(size_t)ROWS * EMBED];
__device__ float g_m1[(size_t)ROWS * MLPDIM];

// ---------------------------------------------------------------------------
// Helpers: fp32 -> tf32 bit pattern, and m16n8k8 tf32 MMA
// ---------------------------------------------------------------------------
__device__ __forceinline__ uint32_t f2tf(float x) {
    uint32_t r;
    asm("cvt.rna.tf32.f32 %0, %1;" : "=r"(r) : "f"(x));
    return r;
}

__device__ __forceinline__ void mma_tf32(float c[4],
                                         const uint32_t a[4],
                                         const uint32_t b[2]) {
    asm volatile(
        "mma.sync.aligned.m16n8k8.row.col.f32.tf32.tf32.f32 "
        "{%0,%1,%2,%3}, {%4,%5,%6,%7}, {%8,%9}, {%0,%1,%2,%3};"
        : "+f"(c[0]), "+f"(c[1]), "+f"(c[2]), "+f"(c[3])
        : "r"(a[0]), "r"(a[1]), "r"(a[2]), "r"(a[3]),
          "r"(b[0]), "r"(b[1]));
}

// ---------------------------------------------------------------------------
// LayerNorm: one block per row (768 elems, 256 threads x 3)
// ---------------------------------------------------------------------------
__global__ __launch_bounds__(256)
void ln_kernel(const float* __restrict__ x, const float* __restrict__ g,
               const float* __restrict__ b, float* __restrict__ out)
{
    __shared__ float s1[8], s2[8];
    const long row = blockIdx.x;
    const float* p = x + row * EMBED;
    const int tid = threadIdx.x;

    float v0 = p[tid], v1 = p[tid + 256], v2 = p[tid + 512];
    float s = v0 + v1 + v2;
    float q = v0 * v0 + v1 * v1 + v2 * v2;
    #pragma unroll
    for (int o = 16; o; o >>= 1) {
        s += __shfl_xor_sync(0xFFFFFFFFu, s, o);
        q += __shfl_xor_sync(0xFFFFFFFFu, q, o);
    }
    if ((tid & 31) == 0) { s1[tid >> 5] = s; s2[tid >> 5] = q; }
    __syncthreads();
    if (tid < 32) {
        s = (tid < 8) ? s1[tid] : 0.0f;
        q = (tid < 8) ? s2[tid] : 0.0f;
        #pragma unroll
        for (int o = 4; o; o >>= 1) {
            s += __shfl_xor_sync(0xFFFFFFFFu, s, o);
            q += __shfl_xor_sync(0xFFFFFFFFu, q, o);
        }
        if (tid == 0) { s1[0] = s; s2[0] = q; }
    }
    __syncthreads();
    const float inv = 1.0f / (float)EMBED;
    const float mu  = s1[0] * inv;
    const float var = s2[0] * inv - mu * mu;
    const float rstd = rsqrtf(var + 1e-5f);
    float* po = out + row * EMBED;
    po[tid      ] = (v0 - mu) * rstd * g[tid      ] + b[tid      ];
    po[tid + 256] = (v1 - mu) * rstd * g[tid + 256] + b[tid + 256];
    po[tid + 512] = (v2 - mu) * rstd * g[tid + 512] + b[tid + 512];
}

// ---------------------------------------------------------------------------
// TF32 tensor-core GEMM: C[M,N] = A[M,K] @ B[K,N] (+ epilogue)
// 128x128 block tile, BK=32, 256 threads (8 warps, 2x4), warp tile 64x32.
// Each warp: 4x4 grid of m16n8k8 mma tiles.
// ---------------------------------------------------------------------------
#define EPI_NONE     0
#define EPI_BIAS     1
#define EPI_GELU     2
#define EPI_BIASRES  3

template<int EPI>
__global__ __launch_bounds__(256)
void gemm_tf32(const float* __restrict__ A, const float* __restrict__ B,
               const float* __restrict__ bias, const float* __restrict__ res,
               float* __restrict__ C, int M, int N, int K)
{
    __shared__ uint32_t As[32][136];   // [k][m], +8 pad => conflict-free frags
    __shared__ uint32_t Bs[32][136];   // [k][n]

    const int tid  = threadIdx.x;
    const int bm   = blockIdx.y * 128;
    const int bn   = blockIdx.x * 128;
    const int w    = tid >> 5;
    const int lane = tid & 31;
    const int m0   = (w >> 2) * 64;    // warp row offset (0 or 64)
    const int n0   = (w & 3) * 32;     // warp col offset (0..96)
    const int g    = lane >> 2;        // 0..7
    const int tq   = lane & 3;         // 0..3

    // loaders
    const int ar = tid >> 1;           // A row 0..127
    const int aq = (tid & 1) * 16;     // A k-offset 0/16
    const int br = tid >> 5;           // B k-row 0..7
    const int bc = (tid & 31) * 4;     // B col 0..124

    float acc[4][4][4];
    #pragma unroll
    for (int i = 0; i < 4; i++)
        #pragma unroll
        for (int j = 0; j < 4; j++)
            #pragma unroll
            for (int r = 0; r < 4; r++) acc[i][j][r] = 0.0f;

    for (int k0 = 0; k0 < K; k0 += 32) {
        // load + convert A tile (128 x 32) transposed into As[k][m]
        #pragma unroll
        for (int kq = 0; kq < 16; kq += 4) {
            float4 av = *(const float4*)(A + (long)(bm + ar) * K + k0 + aq + kq);
            As[aq + kq + 0][ar] = f2tf(av.x);
            As[aq + kq + 1][ar] = f2tf(av.y);
            As[aq + kq + 2][ar] = f2tf(av.z);
            As[aq + kq + 3][ar] = f2tf(av.w);
        }
        // load + convert B tile (32 x 128) into Bs[k][n]
        #pragma unroll
        for (int r8 = 0; r8 < 32; r8 += 8) {
            float4 bv = *(const float4*)(B + (long)(k0 + br + r8) * N + bn + bc);
            uint4 u;
            u.x = f2tf(bv.x); u.y = f2tf(bv.y); u.z = f2tf(bv.z); u.w = f2tf(bv.w);
            *(uint4*)&Bs[br + r8][bc] = u;
        }
        __syncthreads();

        #pragma unroll
        for (int kk = 0; kk < 32; kk += 8) {
            uint32_t af[4][4];
            uint32_t bf[4][2];
            #pragma unroll
            for (int i = 0; i < 4; i++) {
                const int mb = m0 + i * 16;
                af[i][0] = As[kk + tq    ][mb + g    ];
                af[i][1] = As[kk + tq    ][mb + g + 8];
                af[i][2] = As[kk + tq + 4][mb + g    ];
                af[i][3] = As[kk + tq + 4][mb + g + 8];
            }
            #pragma unroll
            for (int j = 0; j < 4; j++) {
                const int nb = n0 + j * 8;
                bf[j][0] = Bs[kk + tq    ][nb + g];
                bf[j][1] = Bs[kk + tq + 4][nb + g];
            }
            #pragma unroll
            for (int i = 0; i < 4; i++)
                #pragma unroll
                for (int j = 0; j < 4; j++)
                    mma_tf32(acc[i][j], af[i], bf[j]);
        }
        __syncthreads();
    }

    // epilogue: thread owns rows (m0+i*16+g, +8), cols (n0+j*8+2*tq, +1)
    #pragma unroll
    for (int i = 0; i < 4; i++) {
        const int row0 = bm + m0 + i * 16 + g;
        #pragma unroll
        for (int j = 0; j < 4; j++) {
            const int col = bn + n0 + j * 8 + tq * 2;
            float b0 = 0.0f, b1 = 0.0f;
            if (EPI != EPI_NONE) { b0 = bias[col]; b1 = bias[col + 1]; }
            #pragma unroll
            for (int half = 0; half < 2; half++) {
                const long base = (long)(row0 + half * 8) * N + col;
                float c0 = acc[i][j][half * 2 + 0];
                float c1 = acc[i][j][half * 2 + 1];
                if (EPI != EPI_NONE) { c0 += b0; c1 += b1; }
                if (EPI == EPI_GELU) {
                    c0 = 0.5f * c0 * (1.0f + erff(c0 * 0.70710678118654752f));
                    c1 = 0.5f * c1 * (1.0f + erff(c1 * 0.70710678118654752f));
                }
                if (EPI == EPI_BIASRES) { c0 += res[base]; c1 += res[base + 1]; }
                float2 o; o.x = c0; o.y = c1;
                *(float2*)(C + base) = o;
            }
        }
    }
}

// ---------------------------------------------------------------------------
// Attention scores: S[bh, n, m] = (Q[bh,n,:] . K[bh,m,:]) / 8
// ---------------------------------------------------------------------------
__global__ __launch_bounds__(256)
void attn_scores(const float* __restrict__ qk, float* __restrict__ sc)
{
    const int bh = blockIdx.z;
    const int b = bh / HEADS, h = bh % HEADS;
    const float* Qb = qk + (long)b * SEQ * QKDIM + h * HDIM;
    const float* Kb = Qb + EMBED;
    const int n0 = blockIdx.y * 64;
    const int m0 = blockIdx.x * 64;
    const int tid = threadIdx.x;

    __shared__ float Qs[64][65];
    __shared__ float Ks[64][65];

    #pragma unroll
    for (int i = 0; i < 4; i++) {
        int idx = tid + i * 256;
        int r = idx >> 4;
        int c = (idx & 15) * 4;
        float4 qv = *(const float4*)(Qb + (long)(n0 + r) * QKDIM + c);
        Qs[r][c] = qv.x; Qs[r][c+1] = qv.y; Qs[r][c+2] = qv.z; Qs[r][c+3] = qv.w;
        float4 kv = *(const float4*)(Kb + (long)(m0 + r) * QKDIM + c);
        Ks[r][c] = kv.x; Ks[r][c+1] = kv.y; Ks[r][c+2] = kv.z; Ks[r][c+3] = kv.w;
    }
    __syncthreads();

    const int tx = tid & 15, ty = tid >> 4;
    float acc[4][4];
    #pragma unroll
    for (int i = 0; i < 4; i++)
        #pragma unroll
        for (int j = 0; j < 4; j++) acc[i][j] = 0.0f;

    #pragma unroll 8
    for (int d = 0; d < HDIM; d++) {
        float a[4], bb[4];
        #pragma unroll
        for (int i = 0; i < 4; i++) a[i]  = Qs[ty * 4 + i][d];
        #pragma unroll
        for (int j = 0; j < 4; j++) bb[j] = Ks[tx * 4 + j][d];
        #pragma unroll
        for (int i = 0; i < 4; i++)
            #pragma unroll
            for (int j = 0; j < 4; j++)
                acc[i][j] = fmaf(a[i], bb[j], acc[i][j]);
    }

    #pragma unroll
    for (int i = 0; i < 4; i++) {
        float out[4];
        #pragma unroll
        for (int j = 0; j < 4; j++) out[j] = acc[i][j] * 0.125f;
        long base = ((long)bh * SEQ + n0 + ty * 4 + i) * SEQ + m0 + tx * 4;
        *(float4*)(sc + base) = *(float4*)&out[0];
    }
}

// ---------------------------------------------------------------------------
// Row softmax over 1024 elements. One block per row, 256 threads x 4.
// ---------------------------------------------------------------------------
__global__ __launch_bounds__(256)
void softmax_rows(float* __restrict__ sc)
{
    __shared__ float sh[8];
    __shared__ float bcast;
    const long row = blockIdx.x;
    float* p = sc + row * SEQ;
    const int tid = threadIdx.x;

    float4 v = *(float4*)(p + tid * 4);
    float m = fmaxf(fmaxf(v.x, v.y), fmaxf(v.z, v.w));
    #pragma unroll
    for (int o = 16; o; o >>= 1) m = fmaxf(m, __shfl_xor_sync(0xFFFFFFFFu, m, o));
    if ((tid & 31) == 0) sh[tid >> 5] = m;
    __syncthreads();
    if (tid < 32) {
        m = (tid < 8) ? sh[tid] : -INFINITY;
        #pragma unroll
        for (int o = 4; o; o >>= 1) m = fmaxf(m, __shfl_xor_sync(0xFFFFFFFFu, m, o));
        if (tid == 0) bcast = m;
    }
    __syncthreads();
    m = bcast;

    v.x = __expf(v.x - m); v.y = __expf(v.y - m);
    v.z = __expf(v.z - m); v.w = __expf(v.w - m);
    float s = v.x + v.y + v.z + v.w;
    #pragma unroll
    for (int o = 16; o; o >>= 1) s += __shfl_xor_sync(0xFFFFFFFFu, s, o);
    __syncthreads();
    if ((tid & 31) == 0) sh[tid >> 5] = s;
    __syncthreads();
    if (tid < 32) {
        s = (tid < 8) ? sh[tid] : 0.0f;
        #pragma unroll
        for (int o = 4; o; o >>= 1) s += __shfl_xor_sync(0xFFFFFFFFu, s, o);
        if (tid == 0) bcast = s;
    }
    __syncthreads();
    const float inv = 1.0f / bcast;
    v.x *= inv; v.y *= inv; v.z *= inv; v.w *= inv;
    *(float4*)(p + tid * 4) = v;
}

// ---------------------------------------------------------------------------
// O = softmax(S) @ V, written in head-merged [ROWS, EMBED] layout.
// ---------------------------------------------------------------------------
__global__ __launch_bounds__(256)
void attn_av(const float* __restrict__ sc, const float* __restrict__ v,
             float* __restrict__ out)
{
    const int bh = blockIdx.y;
    const int b = bh / HEADS, h = bh % HEADS;
    const int n0 = blockIdx.x * 64;
    const float* S  = sc + (long)bh * SEQ * SEQ;
    const float* Vb = v + (long)b * SEQ * EMBED + h * HDIM;
    const int tid = threadIdx.x;
    const int tx = tid & 15, ty = tid >> 4;

    __shared__ float Ss[64][65];
    __shared__ float Vs[64][65];

    float acc[4][4];
    #pragma unroll
    for (int i = 0; i < 4; i++)
        #pragma unroll
        for (int j = 0; j < 4; j++) acc[i][j] = 0.0f;

    for (int m0 = 0; m0 < SEQ; m0 += 64) {
        #pragma unroll
        for (int i = 0; i < 4; i++) {
            int idx = tid + i * 256;
            int r = idx >> 4;
            int c = (idx & 15) * 4;
            float4 sv = *(const float4*)(S + (long)(n0 + r) * SEQ + m0 + c);
            Ss[r][c] = sv.x; Ss[r][c+1] = sv.y; Ss[r][c+2] = sv.z; Ss[r][c+3] = sv.w;
            float4 vv = *(const float4*)(Vb + (long)(m0 + r) * EMBED + c);
            Vs[r][c] = vv.x; Vs[r][c+1] = vv.y; Vs[r][c+2] = vv.z; Vs[r][c+3] = vv.w;
        }
        __syncthreads();

        #pragma unroll 8
        for (int kk = 0; kk < 64; kk++) {
            float a[4], bb[4];
            #pragma unroll
            for (int i = 0; i < 4; i++) a[i]  = Ss[ty * 4 + i][kk];
            #pragma unroll
            for (int j = 0; j < 4; j++) bb[j] = Vs[kk][tx * 4 + j];
            #pragma unroll
            for (int i = 0; i < 4; i++)
                #pragma unroll
                for (int j = 0; j < 4; j++)
                    acc[i][j] = fmaf(a[i], bb[j], acc[i][j]);
        }
        __syncthreads();
    }

    #pragma unroll
    for (int i = 0; i < 4; i++) {
        long base = (long)(b * SEQ + n0 + ty * 4 + i) * EMBED + h * HDIM + tx * 4;
        *(float4*)(out + base) = *(float4*)&acc[i][0];
    }
}

// ---------------------------------------------------------------------------
// Launch
// ---------------------------------------------------------------------------
extern "C" void kernel_launch(void* const* d_in, const int* in_sizes, int n_in,
                              void* d_out, int out_size)
{
    const float* x      = (const float*)d_in[0];
    const float* ln1_g  = (const float*)d_in[1];
    const float* ln1_b  = (const float*)d_in[2];
    const float* qk_w   = (const float*)d_in[3];
    const float* v_w    = (const float*)d_in[4];
    const float* proj_w = (const float*)d_in[5];
    const float* proj_b = (const float*)d_in[6];
    const float* ln2_g  = (const float*)d_in[7];
    const float* ln2_b  = (const float*)d_in[8];
    const float* fc1_w  = (const float*)d_in[9];
    const float* fc1_b  = (const float*)d_in[10];
    const float* fc2_w  = (const float*)d_in[11];
    const float* fc2_b  = (const float*)d_in[12];
    float* out = (float*)d_out;

    float *h1, *qkb, *vb, *sc, *att, *x2, *h2, *m1;
    cudaGetSymbolAddress((void**)&h1,  g_h1);
    cudaGetSymbolAddress((void**)&qkb, g_qk);
    cudaGetSymbolAddress((void**)&vb,  g_v);
    cudaGetSymbolAddress((void**)&sc,  g_sc);
    cudaGetSymbolAddress((void**)&att, g_att);
    cudaGetSymbolAddress((void**)&x2,  g_x2);
    cudaGetSymbolAddress((void**)&h2,  g_h2);
    cudaGetSymbolAddress((void**)&m1,  g_m1);

    // --- attention branch ---
    ln_kernel<<<ROWS, 256>>>(x, ln1_g, ln1_b, h1);

    gemm_tf32<EPI_NONE><<<dim3(QKDIM / 128, ROWS / 128), 256>>>(
        h1, qk_w, nullptr, nullptr, qkb, ROWS, QKDIM, EMBED);
    gemm_tf32<EPI_NONE><<<dim3(EMBED / 128, ROWS / 128), 256>>>(
        h1, v_w, nullptr, nullptr, vb, ROWS, EMBED, EMBED);

    attn_scores<<<dim3(SEQ / 64, SEQ / 64, BH), 256>>>(qkb, sc);
    softmax_rows<<<(long)BH * SEQ, 256>>>(sc);
    attn_av<<<dim3(SEQ / 64, BH), 256>>>(sc, vb, att);

    gemm_tf32<EPI_BIASRES><<<dim3(EMBED / 128, ROWS / 128), 256>>>(
        att, proj_w, proj_b, x, x2, ROWS, EMBED, EMBED);

    // --- MLP branch ---
    ln_kernel<<<ROWS, 256>>>(x2, ln2_g, ln2_b, h2);

    gemm_tf32<EPI_GELU><<<dim3(MLPDIM / 128, ROWS / 128), 256>>>(
        h2, fc1_w, fc1_b, nullptr, m1, ROWS, MLPDIM, EMBED);

    gemm_tf32<EPI_BIASRES><<<dim3(EMBED / 128, ROWS / 128), 256>>>(
        m1, fc2_w, fc2_b, x2, out, ROWS, EMBED, MLPDIM);
}

// round 3
// speedup vs baseline: 3.0145x; 1.4867x over previous
#include <cuda_runtime.h>
#include <cuda_bf16.h>
#include <math.h>
#include <stdint.h>

// ---------------------------------------------------------------------------
// Problem constants
// ---------------------------------------------------------------------------
#define BATCH   8
#define SEQ     1024
#define ROWS    (BATCH * SEQ)        // 8192
#define EMBED   768
#define HEADS   12
#define HDIM    64
#define QKDIM   (2 * EMBED)          // 1536
#define MLPDIM  3072
#define BH      (BATCH * HEADS)      // 96

// ---------------------------------------------------------------------------
// Device scratch (static globals — allocation-free)
// ---------------------------------------------------------------------------
__device__ float g_h1[(size_t)ROWS * EMBED];
__device__ float g_qk[(size_t)ROWS * QKDIM];
__device__ float g_v [(size_t)ROWS * EMBED];
__device__ float g_att[(size_t)ROWS * EMBED];
__device__ float g_x2[(size_t)ROWS * EMBED];
__device__ float g_h2[(size_t)ROWS * EMBED];
__device__ float g_m1[(size_t)ROWS * MLPDIM];

// ---------------------------------------------------------------------------
// Helpers
// ---------------------------------------------------------------------------
__device__ __forceinline__ uint32_t f2tf(float x) {
    uint32_t r;
    asm("cvt.rna.tf32.f32 %0, %1;" : "=r"(r) : "f"(x));
    return r;
}

__device__ __forceinline__ void mma_tf32(float c[4],
                                         const uint32_t a[4],
                                         const uint32_t b[2]) {
    asm volatile(
        "mma.sync.aligned.m16n8k8.row.col.f32.tf32.tf32.f32 "
        "{%0,%1,%2,%3}, {%4,%5,%6,%7}, {%8,%9}, {%0,%1,%2,%3};"
        : "+f"(c[0]), "+f"(c[1]), "+f"(c[2]), "+f"(c[3])
        : "r"(a[0]), "r"(a[1]), "r"(a[2]), "r"(a[3]),
          "r"(b[0]), "r"(b[1]));
}

// ---------------------------------------------------------------------------
// LayerNorm: one block per row
// ---------------------------------------------------------------------------
__global__ __launch_bounds__(256)
void ln_kernel(const float* __restrict__ x, const float* __restrict__ g,
               const float* __restrict__ b, float* __restrict__ out)
{
    __shared__ float s1[8], s2[8];
    const long row = blockIdx.x;
    const float* p = x + row * EMBED;
    const int tid = threadIdx.x;

    float v0 = p[tid], v1 = p[tid + 256], v2 = p[tid + 512];
    float s = v0 + v1 + v2;
    float q = v0 * v0 + v1 * v1 + v2 * v2;
    #pragma unroll
    for (int o = 16; o; o >>= 1) {
        s += __shfl_xor_sync(0xFFFFFFFFu, s, o);
        q += __shfl_xor_sync(0xFFFFFFFFu, q, o);
    }
    if ((tid & 31) == 0) { s1[tid >> 5] = s; s2[tid >> 5] = q; }
    __syncthreads();
    if (tid < 32) {
        s = (tid < 8) ? s1[tid] : 0.0f;
        q = (tid < 8) ? s2[tid] : 0.0f;
        #pragma unroll
        for (int o = 4; o; o >>= 1) {
            s += __shfl_xor_sync(0xFFFFFFFFu, s, o);
            q += __shfl_xor_sync(0xFFFFFFFFu, q, o);
        }
        if (tid == 0) { s1[0] = s; s2[0] = q; }
    }
    __syncthreads();
    const float inv = 1.0f / (float)EMBED;
    const float mu  = s1[0] * inv;
    const float var = s2[0] * inv - mu * mu;
    const float rstd = rsqrtf(var + 1e-5f);
    float* po = out + row * EMBED;
    po[tid      ] = (v0 - mu) * rstd * g[tid      ] + b[tid      ];
    po[tid + 256] = (v1 - mu) * rstd * g[tid + 256] + b[tid + 256];
    po[tid + 512] = (v2 - mu) * rstd * g[tid + 512] + b[tid + 512];
}

// ---------------------------------------------------------------------------
// TF32 tensor-core GEMM (unchanged from R2 — it validated)
// ---------------------------------------------------------------------------
#define EPI_NONE     0
#define EPI_BIAS     1
#define EPI_GELU     2
#define EPI_BIASRES  3

template<int EPI>
__global__ __launch_bounds__(256)
void gemm_tf32(const float* __restrict__ A, const float* __restrict__ B,
               const float* __restrict__ bias, const float* __restrict__ res,
               float* __restrict__ C, int M, int N, int K)
{
    __shared__ uint32_t As[32][136];
    __shared__ uint32_t Bs[32][136];

    const int tid  = threadIdx.x;
    const int bm   = blockIdx.y * 128;
    const int bn   = blockIdx.x * 128;
    const int w    = tid >> 5;
    const int lane = tid & 31;
    const int m0   = (w >> 2) * 64;
    const int n0   = (w & 3) * 32;
    const int g    = lane >> 2;
    const int tq   = lane & 3;

    const int ar = tid >> 1;
    const int aq = (tid & 1) * 16;
    const int br = tid >> 5;
    const int bc = (tid & 31) * 4;

    float acc[4][4][4];
    #pragma unroll
    for (int i = 0; i < 4; i++)
        #pragma unroll
        for (int j = 0; j < 4; j++)
            #pragma unroll
            for (int r = 0; r < 4; r++) acc[i][j][r] = 0.0f;

    for (int k0 = 0; k0 < K; k0 += 32) {
        #pragma unroll
        for (int kq = 0; kq < 16; kq += 4) {
            float4 av = *(const float4*)(A + (long)(bm + ar) * K + k0 + aq + kq);
            As[aq + kq + 0][ar] = f2tf(av.x);
            As[aq + kq + 1][ar] = f2tf(av.y);
            As[aq + kq + 2][ar] = f2tf(av.z);
            As[aq + kq + 3][ar] = f2tf(av.w);
        }
        #pragma unroll
        for (int r8 = 0; r8 < 32; r8 += 8) {
            float4 bv = *(const float4*)(B + (long)(k0 + br + r8) * N + bn + bc);
            uint4 u;
            u.x = f2tf(bv.x); u.y = f2tf(bv.y); u.z = f2tf(bv.z); u.w = f2tf(bv.w);
            *(uint4*)&Bs[br + r8][bc] = u;
        }
        __syncthreads();

        #pragma unroll
        for (int kk = 0; kk < 32; kk += 8) {
            uint32_t af[4][4];
            uint32_t bf[4][2];
            #pragma unroll
            for (int i = 0; i < 4; i++) {
                const int mb = m0 + i * 16;
                af[i][0] = As[kk + tq    ][mb + g    ];
                af[i][1] = As[kk + tq    ][mb + g + 8];
                af[i][2] = As[kk + tq + 4][mb + g    ];
                af[i][3] = As[kk + tq + 4][mb + g + 8];
            }
            #pragma unroll
            for (int j = 0; j < 4; j++) {
                const int nb = n0 + j * 8;
                bf[j][0] = Bs[kk + tq    ][nb + g];
                bf[j][1] = Bs[kk + tq + 4][nb + g];
            }
            #pragma unroll
            for (int i = 0; i < 4; i++)
                #pragma unroll
                for (int j = 0; j < 4; j++)
                    mma_tf32(acc[i][j], af[i], bf[j]);
        }
        __syncthreads();
    }

    #pragma unroll
    for (int i = 0; i < 4; i++) {
        const int row0 = bm + m0 + i * 16 + g;
        #pragma unroll
        for (int j = 0; j < 4; j++) {
            const int col = bn + n0 + j * 8 + tq * 2;
            float b0 = 0.0f, b1 = 0.0f;
            if (EPI != EPI_NONE) { b0 = bias[col]; b1 = bias[col + 1]; }
            #pragma unroll
            for (int half = 0; half < 2; half++) {
                const long base = (long)(row0 + half * 8) * N + col;
                float c0 = acc[i][j][half * 2 + 0];
                float c1 = acc[i][j][half * 2 + 1];
                if (EPI != EPI_NONE) { c0 += b0; c1 += b1; }
                if (EPI == EPI_GELU) {
                    c0 = 0.5f * c0 * (1.0f + erff(c0 * 0.70710678118654752f));
                    c1 = 0.5f * c1 * (1.0f + erff(c1 * 0.70710678118654752f));
                }
                if (EPI == EPI_BIASRES) { c0 += res[base]; c1 += res[base + 1]; }
                float2 o; o.x = c0; o.y = c1;
                *(float2*)(C + base) = o;
            }
        }
    }
}

// ---------------------------------------------------------------------------
// Fused flash attention (tf32 tensor cores, online softmax).
// Grid: (SEQ/128, BH). Block: 256 threads = 8 warps; warp w owns q rows
// [w*16, w*16+16) of the 128-row tile. KV processed in 64-key tiles.
//
// Dynamic smem (uint32 words):
//   Qs [64][136]  k=hdim, m=qrow (tf32, pre-scaled by 1/8)   off 0      8704
//   Ks [64][72]   k=hdim, n=key                               off 8704   4608
//   Vs [64][76]   k=key,  n=hdim                              off 13312  4864
//   Ps 8 x [16][68] per-warp P staging                        off 18176  8704
// total 26880 words = 107520 bytes
// ---------------------------------------------------------------------------
#define FA_SMEM_BYTES 107520

__global__ __launch_bounds__(256)
void flash_attn(const float* __restrict__ qk, const float* __restrict__ vbuf,
                float* __restrict__ out)
{
    extern __shared__ uint32_t sm[];
    uint32_t* Qs = sm;
    uint32_t* Ks = sm + 8704;
    uint32_t* Vs = sm + 13312;
    uint32_t* Ps = sm + 18176;

    const int bh = blockIdx.y;
    const int b  = bh / HEADS, h = bh % HEADS;
    const int q0 = blockIdx.x * 128;
    const int tid  = threadIdx.x;
    const int w    = tid >> 5;
    const int lane = tid & 31;
    const int g    = lane >> 2;
    const int tq   = lane & 3;
    uint32_t* Pw = Ps + w * (16 * 68);

    const float* Qg = qk + (long)b * SEQ * QKDIM + h * HDIM;
    const float* Kg = Qg + EMBED;
    const float* Vg = vbuf + (long)b * SEQ * EMBED + h * HDIM;

    // ---- load Q tile (128 x 64), scale 1/8, transpose -> Qs[k][m] ----
    {
        const int ar = tid >> 1;
        const int aq = (tid & 1) * 32;
        const float* src = Qg + (long)(q0 + ar) * QKDIM + aq;
        #pragma unroll
        for (int i = 0; i < 32; i += 4) {
            float4 v = *(const float4*)(src + i);
            Qs[(aq + i + 0) * 136 + ar] = f2tf(v.x * 0.125f);
            Qs[(aq + i + 1) * 136 + ar] = f2tf(v.y * 0.125f);
            Qs[(aq + i + 2) * 136 + ar] = f2tf(v.z * 0.125f);
            Qs[(aq + i + 3) * 136 + ar] = f2tf(v.w * 0.125f);
        }
    }

    float oacc[8][4];
    #pragma unroll
    for (int j = 0; j < 8; j++)
        #pragma unroll
        for (int r = 0; r < 4; r++) oacc[j][r] = 0.0f;
    float mrow0 = -INFINITY, mrow1 = -INFINITY;
    float lrow0 = 0.0f, lrow1 = 0.0f;

    for (int kv = 0; kv < SEQ; kv += 64) {
        __syncthreads();   // protect Ks/Vs against previous iteration's reads
        // ---- load K tile (64 keys x 64 dims), transpose -> Ks[k][n] ----
        {
            const int kr = tid & 63;
            const int kq = (tid >> 6) * 16;
            const float* src = Kg + (long)(kv + kr) * QKDIM + kq;
            #pragma unroll
            for (int i = 0; i < 16; i += 4) {
                float4 v = *(const float4*)(src + i);
                Ks[(kq + i + 0) * 72 + kr] = f2tf(v.x);
                Ks[(kq + i + 1) * 72 + kr] = f2tf(v.y);
                Ks[(kq + i + 2) * 72 + kr] = f2tf(v.z);
                Ks[(kq + i + 3) * 72 + kr] = f2tf(v.w);
            }
        }
        // ---- load V tile (64 keys x 64 dims), natural -> Vs[k][n] ----
        {
            const int vr = tid >> 2;
            const int vq = (tid & 3) * 16;
            const float* src = Vg + (long)(kv + vr) * EMBED + vq;
            #pragma unroll
            for (int i = 0; i < 16; i += 4) {
                float4 v = *(const float4*)(src + i);
                uint4 u;
                u.x = f2tf(v.x); u.y = f2tf(v.y); u.z = f2tf(v.z); u.w = f2tf(v.w);
                *(uint4*)&Vs[vr * 76 + vq + i] = u;
            }
        }
        __syncthreads();

        // ---- S = (Q/8) @ K^T : warp computes 16 x 64 scores ----
        float sacc[8][4];
        #pragma unroll
        for (int j = 0; j < 8; j++)
            #pragma unroll
            for (int r = 0; r < 4; r++) sacc[j][r] = 0.0f;

        #pragma unroll
        for (int kk = 0; kk < 64; kk += 8) {
            uint32_t af[4];
            const int mb = w * 16;
            af[0] = Qs[(kk + tq    ) * 136 + mb + g    ];
            af[1] = Qs[(kk + tq    ) * 136 + mb + g + 8];
            af[2] = Qs[(kk + tq + 4) * 136 + mb + g    ];
            af[3] = Qs[(kk + tq + 4) * 136 + mb + g + 8];
            #pragma unroll
            for (int j = 0; j < 8; j++) {
                uint32_t bf[2];
                bf[0] = Ks[(kk + tq    ) * 72 + j * 8 + g];
                bf[1] = Ks[(kk + tq + 4) * 72 + j * 8 + g];
                mma_tf32(sacc[j], af, bf);
            }
        }

        // ---- online softmax (rows g and g+8) ----
        float tmax0 = -INFINITY, tmax1 = -INFINITY;
        #pragma unroll
        for (int j = 0; j < 8; j++) {
            tmax0 = fmaxf(tmax0, fmaxf(sacc[j][0], sacc[j][1]));
            tmax1 = fmaxf(tmax1, fmaxf(sacc[j][2], sacc[j][3]));
        }
        #pragma unroll
        for (int o = 1; o < 4; o <<= 1) {
            tmax0 = fmaxf(tmax0, __shfl_xor_sync(0xFFFFFFFFu, tmax0, o));
            tmax1 = fmaxf(tmax1, __shfl_xor_sync(0xFFFFFFFFu, tmax1, o));
        }
        const float mnew0 = fmaxf(mrow0, tmax0);
        const float mnew1 = fmaxf(mrow1, tmax1);
        const float alpha0 = __expf(mrow0 - mnew0);
        const float alpha1 = __expf(mrow1 - mnew1);
        mrow0 = mnew0; mrow1 = mnew1;

        float sum0 = 0.0f, sum1 = 0.0f;
        #pragma unroll
        for (int j = 0; j < 8; j++) {
            sacc[j][0] = __expf(sacc[j][0] - mnew0);
            sacc[j][1] = __expf(sacc[j][1] - mnew0);
            sacc[j][2] = __expf(sacc[j][2] - mnew1);
            sacc[j][3] = __expf(sacc[j][3] - mnew1);
            sum0 += sacc[j][0] + sacc[j][1];
            sum1 += sacc[j][2] + sacc[j][3];
        }
        #pragma unroll
        for (int o = 1; o < 4; o <<= 1) {
            sum0 += __shfl_xor_sync(0xFFFFFFFFu, sum0, o);
            sum1 += __shfl_xor_sync(0xFFFFFFFFu, sum1, o);
        }
        lrow0 = lrow0 * alpha0 + sum0;
        lrow1 = lrow1 * alpha1 + sum1;

        #pragma unroll
        for (int j = 0; j < 8; j++) {
            oacc[j][0] *= alpha0; oacc[j][1] *= alpha0;
            oacc[j][2] *= alpha1; oacc[j][3] *= alpha1;
        }

        // ---- stage P (tf32) to per-warp smem ----
        #pragma unroll
        for (int j = 0; j < 8; j++) {
            Pw[ g      * 68 + j * 8 + tq * 2    ] = f2tf(sacc[j][0]);
            Pw[ g      * 68 + j * 8 + tq * 2 + 1] = f2tf(sacc[j][1]);
            Pw[(g + 8) * 68 + j * 8 + tq * 2    ] = f2tf(sacc[j][2]);
            Pw[(g + 8) * 68 + j * 8 + tq * 2 + 1] = f2tf(sacc[j][3]);
        }
        __syncwarp();

        // ---- O += P @ V ----
        #pragma unroll
        for (int kk = 0; kk < 64; kk += 8) {
            uint32_t af[4];
            af[0] = Pw[ g      * 68 + kk + tq    ];
            af[1] = Pw[(g + 8) * 68 + kk + tq    ];
            af[2] = Pw[ g      * 68 + kk + tq + 4];
            af[3] = Pw[(g + 8) * 68 + kk + tq + 4];
            #pragma unroll
            for (int j = 0; j < 8; j++) {
                uint32_t bf[2];
                bf[0] = Vs[(kk + tq    ) * 76 + j * 8 + g];
                bf[1] = Vs[(kk + tq + 4) * 76 + j * 8 + g];
                mma_tf32(oacc[j], af, bf);
            }
        }
        __syncwarp();   // P reads done before next iteration overwrites
    }

    // ---- epilogue: O /= l, write head-merged [ROWS, EMBED] ----
    const float inv0 = 1.0f / lrow0;
    const float inv1 = 1.0f / lrow1;
    const long row0 = (long)(b * SEQ + q0 + w * 16 + g);
    #pragma unroll
    for (int j = 0; j < 8; j++) {
        const int col = h * HDIM + j * 8 + tq * 2;
        float2 o0; o0.x = oacc[j][0] * inv0; o0.y = oacc[j][1] * inv0;
        float2 o1; o1.x = oacc[j][2] * inv1; o1.y = oacc[j][3] * inv1;
        *(float2*)(out + row0 * EMBED + col)       = o0;
        *(float2*)(out + (row0 + 8) * EMBED + col) = o1;
    }
}

// ---------------------------------------------------------------------------
// Launch
// ---------------------------------------------------------------------------
extern "C" void kernel_launch(void* const* d_in, const int* in_sizes, int n_in,
                              void* d_out, int out_size)
{
    const float* x      = (const float*)d_in[0];
    const float* ln1_g  = (const float*)d_in[1];
    const float* ln1_b  = (const float*)d_in[2];
    const float* qk_w   = (const float*)d_in[3];
    const float* v_w    = (const float*)d_in[4];
    const float* proj_w = (const float*)d_in[5];
    const float* proj_b = (const float*)d_in[6];
    const float* ln2_g  = (const float*)d_in[7];
    const float* ln2_b  = (const float*)d_in[8];
    const float* fc1_w  = (const float*)d_in[9];
    const float* fc1_b  = (const float*)d_in[10];
    const float* fc2_w  = (const float*)d_in[11];
    const float* fc2_b  = (const float*)d_in[12];
    float* out = (float*)d_out;

    float *h1, *qkb, *vb, *att, *x2, *h2, *m1;
    cudaGetSymbolAddress((void**)&h1,  g_h1);
    cudaGetSymbolAddress((void**)&qkb, g_qk);
    cudaGetSymbolAddress((void**)&vb,  g_v);
    cudaGetSymbolAddress((void**)&att, g_att);
    cudaGetSymbolAddress((void**)&x2,  g_x2);
    cudaGetSymbolAddress((void**)&h2,  g_h2);
    cudaGetSymbolAddress((void**)&m1,  g_m1);

    static bool attr_done = false;
    if (!attr_done) {
        cudaFuncSetAttribute(flash_attn,
                             cudaFuncAttributeMaxDynamicSharedMemorySize,
                             FA_SMEM_BYTES);
        attr_done = true;
    }

    // --- attention branch ---
    ln_kernel<<<ROWS, 256>>>(x, ln1_g, ln1_b, h1);

    gemm_tf32<EPI_NONE><<<dim3(QKDIM / 128, ROWS / 128), 256>>>(
        h1, qk_w, nullptr, nullptr, qkb, ROWS, QKDIM, EMBED);
    gemm_tf32<EPI_NONE><<<dim3(EMBED / 128, ROWS / 128), 256>>>(
        h1, v_w, nullptr, nullptr, vb, ROWS, EMBED, EMBED);

    flash_attn<<<dim3(SEQ / 128, BH), 256, FA_SMEM_BYTES>>>(qkb, vb, att);

    gemm_tf32<EPI_BIASRES><<<dim3(EMBED / 128, ROWS / 128), 256>>>(
        att, proj_w, proj_b, x, x2, ROWS, EMBED, EMBED);

    // --- MLP branch ---
    ln_kernel<<<ROWS, 256>>>(x2, ln2_g, ln2_b, h2);

    gemm_tf32<EPI_GELU><<<dim3(MLPDIM / 128, ROWS / 128), 256>>>(
        h2, fc1_w, fc1_b, nullptr, m1, ROWS, MLPDIM, EMBED);

    gemm_tf32<EPI_BIASRES><<<dim3(EMBED / 128, ROWS / 128), 256>>>(
        m1, fc2_w, fc2_b, x2, out, ROWS, EMBED, MLPDIM);
}